// round 1
// baseline (speedup 1.0000x reference)
#include <cuda_runtime.h>
#include <cuda_bf16.h>
#include <math.h>

#define HH    14
#define WW    14
#define NN    197
#define BB    8
#define DIMV  64
#define NHEAD 2
#define DH    32
#define NUU   1122
#define NPAIR (NN*NN)   // 38809
#define WLMAX 4096
#define SCALE 0.17677669529663687f

// ---------------- scratch (device globals; no allocations allowed) -------------
__device__ float    g_xn[BB*NN*DIMV];          // 403 KB
__device__ float    g_qk[BB*NN*2*DIMV];        // 806 KB
__device__ float    g_attn[BB*NHEAD*NN*NN];    // 2.48 MB
__device__ float    g_T[(size_t)NPAIR*BB*DIMV];// 79.5 MB  T[n,m,b,e]
__device__ int      g_cnt[NUU];
__device__ int      g_off[NUU+1];
__device__ int      g_cur[NUU];
__device__ unsigned g_pairs[NPAIR];            // sorted by u, packed n<<16|m
__device__ uint2    g_work[WLMAX];             // (pairStart, u<<16|count)
__device__ int      g_nwork;

// ---------------- tiny setup kernels -----------------------------------------
__global__ void k_zero() {
    int i = blockIdx.x*blockDim.x + threadIdx.x;
    if (i < NUU) g_cnt[i] = 0;
}

__global__ void k_hist(const int* __restrict__ imap) {
    int i = blockIdx.x*blockDim.x + threadIdx.x;
    if (i < NPAIR) atomicAdd(&g_cnt[imap[i]], 1);
}

// single block, 1024 threads: scan counts -> offsets; build work list
__global__ void k_plan() {
    __shared__ int sa[2048], sb[2048];
    int t = threadIdx.x;
    int *src = sa, *dst = sb;
    for (int i = t; i < 2048; i += 1024) src[i] = (i < NUU) ? g_cnt[i] : 0;
    __syncthreads();
    for (int off = 1; off < 2048; off <<= 1) {
        for (int i = t; i < 2048; i += 1024)
            dst[i] = src[i] + (i >= off ? src[i-off] : 0);
        __syncthreads();
        int* tmp = src; src = dst; dst = tmp;
    }
    // src = inclusive scan of counts
    for (int i = t; i <= NUU; i += 1024) g_off[i] = (i == 0) ? 0 : src[i-1];
    for (int i = t; i <  NUU; i += 1024) g_cur[i] = (i == 0) ? 0 : src[i-1];
    __syncthreads();
    // second scan: entries per u = ceil(cnt/16)
    for (int i = t; i < 2048; i += 1024) src[i] = (i < NUU) ? ((g_cnt[i] + 15) >> 4) : 0;
    __syncthreads();
    for (int off = 1; off < 2048; off <<= 1) {
        for (int i = t; i < 2048; i += 1024)
            dst[i] = src[i] + (i >= off ? src[i-off] : 0);
        __syncthreads();
        int* tmp = src; src = dst; dst = tmp;
    }
    int total = src[NUU-1];
    for (int u = t; u < NUU; u += 1024) {
        int cnt = g_cnt[u];
        int po  = g_off[u];
        int eo  = (u == 0) ? 0 : src[u-1];
        int j = 0;
        for (int s = 0; s < cnt; s += 16, j++) {
            int idx = eo + j;
            int c = cnt - s; if (c > 16) c = 16;
            if (idx < WLMAX)
                g_work[idx] = make_uint2((unsigned)(po + s),
                                         ((unsigned)u << 16) | (unsigned)c);
        }
    }
    if (t == 0) g_nwork = (total < WLMAX) ? total : WLMAX;
}

__global__ void k_scatter(const int* __restrict__ imap) {
    int i = blockIdx.x*blockDim.x + threadIdx.x;
    if (i >= NPAIR) return;
    int u = imap[i];
    int n = i / NN, m = i % NN;
    int pos = atomicAdd(&g_cur[u], 1);
    g_pairs[pos] = ((unsigned)n << 16) | (unsigned)m;
}

// ---------------- layernorm ---------------------------------------------------
__global__ void k_ln(const float* __restrict__ x, const float* __restrict__ gamma,
                     const float* __restrict__ beta) {
    int row = blockIdx.x;           // b*NN+n
    int t = threadIdx.x;            // 64
    float v = x[row*DIMV + t];
    float sum = v, sq = v*v;
    #pragma unroll
    for (int o = 16; o > 0; o >>= 1) {
        sum += __shfl_down_sync(0xffffffffu, sum, o);
        sq  += __shfl_down_sync(0xffffffffu, sq,  o);
    }
    __shared__ float s1[2], s2[2];
    if ((t & 31) == 0) { s1[t>>5] = sum; s2[t>>5] = sq; }
    __syncthreads();
    float S = s1[0] + s1[1], Q = s2[0] + s2[1];
    float mu  = S * (1.0f/DIMV);
    float var = Q * (1.0f/DIMV) - mu*mu;
    float r   = rsqrtf(var + 1e-5f);
    g_xn[row*DIMV + t] = (v - mu) * r * gamma[t] + beta[t];
}

// ---------------- q,k projection ----------------------------------------------
__global__ void k_qk(const float* __restrict__ wqk) {
    __shared__ float sx[DIMV];
    int row = blockIdx.x;           // b*NN+n
    int t = threadIdx.x;            // 128
    if (t < DIMV) sx[t] = g_xn[row*DIMV + t];
    __syncthreads();
    float acc = 0.f;
    #pragma unroll 8
    for (int d = 0; d < DIMV; d++) acc += sx[d] * wqk[d*128 + t];
    g_qk[row*128 + t] = acc;
}

// ---------------- attention scores + softmax ----------------------------------
// grid = BB * NHEAD * 25 (n-tiles of 8), 256 threads
__global__ void k_attn() {
    __shared__ float ks[NN*33];
    __shared__ float qs[DH];
    __shared__ float red[8];
    __shared__ float bcast;
    int bid = blockIdx.x;
    int b  = bid / (NHEAD*25);
    int r  = bid % (NHEAD*25);
    int h  = r / 25;
    int nt = r % 25;
    int tid = threadIdx.x, lane = tid & 31, wid = tid >> 5;

    for (int i = tid; i < NN*DH; i += 256) {
        int m = i >> 5, d = i & 31;
        ks[m*33 + d] = g_qk[(b*NN + m)*128 + 64 + h*DH + d];
    }
    __syncthreads();

    for (int k0 = 0; k0 < 8; k0++) {
        int n = nt*8 + k0;
        if (n >= NN) break;
        if (tid < DH) qs[tid] = g_qk[(b*NN + n)*128 + h*DH + tid];
        __syncthreads();
        float s = -3.0e38f;
        if (tid < NN) {
            float a = 0.f;
            #pragma unroll 8
            for (int d = 0; d < DH; d++) a += qs[d] * ks[tid*33 + d];
            s = a * SCALE;
        }
        // max reduce
        float loc = s;
        #pragma unroll
        for (int o = 16; o > 0; o >>= 1) loc = fmaxf(loc, __shfl_xor_sync(0xffffffffu, loc, o));
        if (lane == 0) red[wid] = loc;
        __syncthreads();
        if (tid == 0) {
            float m0 = red[0];
            #pragma unroll
            for (int i = 1; i < 8; i++) m0 = fmaxf(m0, red[i]);
            bcast = m0;
        }
        __syncthreads();
        float mx = bcast;
        float p = (tid < NN) ? __expf(s - mx) : 0.f;
        float ls = p;
        #pragma unroll
        for (int o = 16; o > 0; o >>= 1) ls += __shfl_xor_sync(0xffffffffu, ls, o);
        if (lane == 0) red[wid] = ls;
        __syncthreads();
        if (tid == 0) {
            float s0 = 0.f;
            #pragma unroll
            for (int i = 0; i < 8; i++) s0 += red[i];
            bcast = s0;
        }
        __syncthreads();
        float inv = 1.0f / bcast;
        if (tid < NN) g_attn[(((size_t)b*NHEAD + h)*NN + n)*NN + tid] = p * inv;
        __syncthreads();
    }
}

// ---------------- phase 1: T[n,m,b,e] = xn[b,m] . U[idx(n,m)][:,e] -------------
// grid = WLMAX (early exit), 256 threads = 8 warps; each work item = one u,
// <=16 pairs; warp processes pairs p = w, w+8; per pair all 8 batches.
__global__ void __launch_bounds__(256) k_main(const float* __restrict__ up) {
    __shared__ float sU[DIMV*DIMV];     // 16 KB
    __shared__ float sX[8][DIMV][BB];   // 16 KB, per-warp transposed xn stage
    int bid = blockIdx.x;
    if (bid >= g_nwork) return;
    uint2 wk = g_work[bid];
    int pairStart = (int)wk.x;
    int u   = (int)(wk.y >> 16);
    int cnt = (int)(wk.y & 0xffffu);
    const float* Up = up + (size_t)u * (DIMV*DIMV);
    for (int i = threadIdx.x; i < DIMV*DIMV; i += 256) sU[i] = Up[i];
    __syncthreads();

    int w = threadIdx.x >> 5, lane = threadIdx.x & 31;
    int e2 = lane * 2;

    for (int p = w; p < cnt; p += 8) {
        unsigned pk = g_pairs[pairStart + p];
        int n = (int)(pk >> 16), m = (int)(pk & 0xffffu);
        // stage xn[:,m,:] transposed -> sX[w][d][b]
        {
            int b  = lane >> 2;
            int d0 = (lane & 3) * 16;
            const float* xr = g_xn + (b*NN + m)*DIMV + d0;
            #pragma unroll
            for (int j = 0; j < 16; j += 4) {
                float4 v = *(const float4*)(xr + j);
                sX[w][d0+j  ][b] = v.x;
                sX[w][d0+j+1][b] = v.y;
                sX[w][d0+j+2][b] = v.z;
                sX[w][d0+j+3][b] = v.w;
            }
        }
        __syncwarp();
        float acc[BB][2];
        #pragma unroll
        for (int b = 0; b < BB; b++) { acc[b][0] = 0.f; acc[b][1] = 0.f; }
        #pragma unroll 8
        for (int d = 0; d < DIMV; d++) {
            float2 uu = *(const float2*)&sU[d*DIMV + e2];
            float4 xa = *(const float4*)&sX[w][d][0];
            float4 xb = *(const float4*)&sX[w][d][4];
            acc[0][0] += xa.x*uu.x; acc[0][1] += xa.x*uu.y;
            acc[1][0] += xa.y*uu.x; acc[1][1] += xa.y*uu.y;
            acc[2][0] += xa.z*uu.x; acc[2][1] += xa.z*uu.y;
            acc[3][0] += xa.w*uu.x; acc[3][1] += xa.w*uu.y;
            acc[4][0] += xb.x*uu.x; acc[4][1] += xb.x*uu.y;
            acc[5][0] += xb.y*uu.x; acc[5][1] += xb.y*uu.y;
            acc[6][0] += xb.z*uu.x; acc[6][1] += xb.z*uu.y;
            acc[7][0] += xb.w*uu.x; acc[7][1] += xb.w*uu.y;
        }
        __syncwarp();
        int base = (n*NN + m) * (BB*DIMV) + e2;
        #pragma unroll
        for (int b = 0; b < BB; b++) {
            float2 v; v.x = acc[b][0]; v.y = acc[b][1];
            *(float2*)&g_T[base + b*DIMV] = v;
        }
    }
}

// ---------------- phase 2: attn-weighted sum + output projection ---------------
// grid = BB*NN, 64 threads (thread = e / f)
__global__ void k_out(const float* __restrict__ wout, const float* __restrict__ bout,
                      float* __restrict__ out) {
    __shared__ float sA[2*200];
    __shared__ float sAcc[DIMV];
    int bid = blockIdx.x;
    int b = bid / NN, n = bid % NN;
    int e = threadIdx.x;
    for (int i = e; i < 2*NN; i += DIMV) {
        int h = i / NN, m = i % NN;
        sA[h*200 + m] = g_attn[(((size_t)b*NHEAD + h)*NN + n)*NN + m];
    }
    __syncthreads();
    int h = e >> 5;
    const float* Tb = g_T + (size_t)(n*NN) * (BB*DIMV) + b*DIMV + e;
    float acc = 0.f;
    #pragma unroll 4
    for (int m = 0; m < NN; m++) acc += sA[h*200 + m] * Tb[(size_t)m * (BB*DIMV)];
    sAcc[e] = acc;
    __syncthreads();
    float r = bout[e];
    #pragma unroll 8
    for (int k = 0; k < DIMV; k++) r += sAcc[k] * wout[k*DIMV + e];
    out[(b*NN + n)*DIMV + e] = r;
}

// ---------------- launch -------------------------------------------------------
extern "C" void kernel_launch(void* const* d_in, const int* in_sizes, int n_in,
                              void* d_out, int out_size) {
    const float* x     = (const float*)d_in[0];
    const float* gamma = (const float*)d_in[1];
    const float* beta  = (const float*)d_in[2];
    const float* wqk   = (const float*)d_in[3];
    const float* up    = (const float*)d_in[4];
    const float* wout  = (const float*)d_in[5];
    const float* bout  = (const float*)d_in[6];
    const int*   imap  = (const int*)d_in[7];
    float* out = (float*)d_out;

    k_zero   <<<(NUU+255)/256, 256>>>();
    k_hist   <<<(NPAIR+255)/256, 256>>>(imap);
    k_plan   <<<1, 1024>>>();
    k_scatter<<<(NPAIR+255)/256, 256>>>(imap);
    k_ln     <<<BB*NN, 64>>>(x, gamma, beta);
    k_qk     <<<BB*NN, 128>>>(wqk);
    k_attn   <<<BB*NHEAD*25, 256>>>();
    k_main   <<<WLMAX, 256>>>(up);
    k_out    <<<BB*NN, 64>>>(wout, bout, out);
}

// round 2
// speedup vs baseline: 1.0963x; 1.0963x over previous
#include <cuda_runtime.h>
#include <cuda_bf16.h>
#include <math.h>

#define HH    14
#define WW    14
#define NN    197
#define BB    8
#define DIMV  64
#define NHEAD 2
#define DH    32
#define NUU   1122
#define NPAIR (NN*NN)   // 38809
#define RELU_ 729       // 27*27 relative-position uniques
#define RELPAIRS 38416  // 196*196
#define WLMAX 4096
#define SCALE 0.17677669529663687f

typedef unsigned long long ull;

// ---------------- scratch (device globals; no allocations allowed) -------------
__device__ float    g_xn[BB*NN*DIMV];          // 403 KB
__device__ float    g_qk[BB*NN*2*DIMV];        // 806 KB
__device__ float    g_attn[BB*NHEAD*NN*NN];    // 2.48 MB
__device__ float    g_T[(size_t)NPAIR*BB*DIMV];// 79.5 MB  T[n,m,b,e]
__device__ unsigned g_pairs[NPAIR];            // sorted by u, packed n<<16|m
__device__ uint2    g_work[WLMAX];             // (pairStart, u<<16|count)
__device__ int      g_nwork;

// h(a) = count of (x,i) pairs with x-i+13 == a
__device__ __forceinline__ int hfun(int a) { return 14 - abs(a - 13); }
// C(t) = sum_{a<t} h(a)
__device__ __forceinline__ int cfun(int t) {
    return (t <= 13) ? (t*(t+1))/2 : 196 - ((27-t)*(28-t))/2;
}

// ---------------- analytic pair placement (no atomics, no imap) ----------------
__global__ void k_fill() {
    int i = blockIdx.x*blockDim.x + threadIdx.x;
    if (i >= NPAIR) return;
    int n = i / NN, m = i % NN;
    int pos;
    if (n == 0) {
        pos = RELPAIRS + m;                       // u = 729+m, cnt 1
    } else if (m == 0) {
        pos = RELPAIRS + NN + (n - 1);            // u = 926+(n-1), cnt 1
    } else {
        int x = (n-1) / WW, y = (n-1) % WW;
        int ii = (m-1) / WW, jj = (m-1) % WW;
        int dx = x - ii + 13, dy = y - jj + 13;
        int off = cfun(dx)*196 + hfun(dx)*cfun(dy);
        int xmin = max(0, dx-13), ymin = max(0, dy-13);
        int rank = (x - xmin)*hfun(dy) + (y - ymin);
        pos = off + rank;
    }
    g_pairs[pos] = ((unsigned)n << 16) | (unsigned)m;
}

// single block: counts analytic, scan ceil(cnt/16), emit work list
__global__ void k_plan2() {
    __shared__ int sa[2048], sb[2048];
    int t = threadIdx.x;
    int *src = sa, *dst = sb;
    for (int i = t; i < 2048; i += 1024) {
        int c = 0;
        if (i < RELU_)      c = hfun(i/27) * hfun(i%27);
        else if (i < NUU)   c = 1;
        src[i] = (c + 15) >> 4;
    }
    __syncthreads();
    for (int off = 1; off < 2048; off <<= 1) {
        for (int i = t; i < 2048; i += 1024)
            dst[i] = src[i] + (i >= off ? src[i-off] : 0);
        __syncthreads();
        int* tmp = src; src = dst; dst = tmp;
    }
    for (int u = t; u < NUU; u += 1024) {
        int cnt, po;
        if (u < RELU_) {
            int dx = u/27, dy = u%27;
            cnt = hfun(dx)*hfun(dy);
            po  = cfun(dx)*196 + hfun(dx)*cfun(dy);
        } else if (u < RELU_ + NN) {
            cnt = 1; po = RELPAIRS + (u - RELU_);
        } else {
            cnt = 1; po = RELPAIRS + NN + (u - RELU_ - NN);
        }
        int eo = (u == 0) ? 0 : src[u-1];
        int j = 0;
        for (int s = 0; s < cnt; s += 16, j++) {
            int c = cnt - s; if (c > 16) c = 16;
            if (eo + j < WLMAX)
                g_work[eo + j] = make_uint2((unsigned)(po + s),
                                            ((unsigned)u << 16) | (unsigned)c);
        }
    }
    if (t == 0) g_nwork = min(src[NUU-1], WLMAX);
}

// ---------------- layernorm ---------------------------------------------------
__global__ void k_ln(const float* __restrict__ x, const float* __restrict__ gamma,
                     const float* __restrict__ beta) {
    int row = blockIdx.x;           // b*NN+n
    int t = threadIdx.x;            // 64
    float v = x[row*DIMV + t];
    float sum = v, sq = v*v;
    #pragma unroll
    for (int o = 16; o > 0; o >>= 1) {
        sum += __shfl_down_sync(0xffffffffu, sum, o);
        sq  += __shfl_down_sync(0xffffffffu, sq,  o);
    }
    __shared__ float s1[2], s2[2];
    if ((t & 31) == 0) { s1[t>>5] = sum; s2[t>>5] = sq; }
    __syncthreads();
    float S = s1[0] + s1[1], Q = s2[0] + s2[1];
    float mu  = S * (1.0f/DIMV);
    float var = Q * (1.0f/DIMV) - mu*mu;
    float r   = rsqrtf(var + 1e-5f);
    g_xn[row*DIMV + t] = (v - mu) * r * gamma[t] + beta[t];
}

// ---------------- q,k projection ----------------------------------------------
__global__ void k_qk(const float* __restrict__ wqk) {
    __shared__ float sx[DIMV];
    int row = blockIdx.x;           // b*NN+n
    int t = threadIdx.x;            // 128
    if (t < DIMV) sx[t] = g_xn[row*DIMV + t];
    __syncthreads();
    float acc = 0.f;
    #pragma unroll 8
    for (int d = 0; d < DIMV; d++) acc += sx[d] * wqk[d*128 + t];
    g_qk[row*128 + t] = acc;
}

// ---------------- attention scores + softmax ----------------------------------
__global__ void k_attn() {
    __shared__ float ks[NN*33];
    __shared__ float qs[DH];
    __shared__ float red[8];
    __shared__ float bcast;
    int bid = blockIdx.x;
    int b  = bid / (NHEAD*25);
    int r  = bid % (NHEAD*25);
    int h  = r / 25;
    int nt = r % 25;
    int tid = threadIdx.x, lane = tid & 31, wid = tid >> 5;

    for (int i = tid; i < NN*DH; i += 256) {
        int m = i >> 5, d = i & 31;
        ks[m*33 + d] = g_qk[(b*NN + m)*128 + 64 + h*DH + d];
    }
    __syncthreads();

    for (int k0 = 0; k0 < 8; k0++) {
        int n = nt*8 + k0;
        if (n >= NN) break;
        if (tid < DH) qs[tid] = g_qk[(b*NN + n)*128 + h*DH + tid];
        __syncthreads();
        float s = -3.0e38f;
        if (tid < NN) {
            float a = 0.f;
            #pragma unroll 8
            for (int d = 0; d < DH; d++) a += qs[d] * ks[tid*33 + d];
            s = a * SCALE;
        }
        float loc = s;
        #pragma unroll
        for (int o = 16; o > 0; o >>= 1) loc = fmaxf(loc, __shfl_xor_sync(0xffffffffu, loc, o));
        if (lane == 0) red[wid] = loc;
        __syncthreads();
        if (tid == 0) {
            float m0 = red[0];
            #pragma unroll
            for (int i = 1; i < 8; i++) m0 = fmaxf(m0, red[i]);
            bcast = m0;
        }
        __syncthreads();
        float mx = bcast;
        float p = (tid < NN) ? __expf(s - mx) : 0.f;
        float ls = p;
        #pragma unroll
        for (int o = 16; o > 0; o >>= 1) ls += __shfl_xor_sync(0xffffffffu, ls, o);
        if (lane == 0) red[wid] = ls;
        __syncthreads();
        if (tid == 0) {
            float s0 = 0.f;
            #pragma unroll
            for (int i = 0; i < 8; i++) s0 += red[i];
            bcast = s0;
        }
        __syncthreads();
        float inv = 1.0f / bcast;
        if (tid < NN) g_attn[(((size_t)b*NHEAD + h)*NN + n)*NN + tid] = p * inv;
        __syncthreads();
    }
}

// ---------------- phase 1: T[n,m,b,e] = xn[b,m] . U[idx(n,m)][:,e] -------------
// Packed f32x2 math: accumulators pair adjacent BATCHES; x pairs come directly
// from the b-contiguous sX stage via uniform LDS.128; u scalar duplicated once.
#define FMA2(acc, a, b) asm("fma.rn.f32x2 %0, %1, %2, %0;" : "+l"(acc) : "l"(a), "l"(b))
#define DUP2(dst, s)    asm("mov.b64 %0, {%1, %1};" : "=l"(dst) : "r"(__float_as_uint(s)))

__global__ void __launch_bounds__(256) k_main(const float* __restrict__ up) {
    __shared__ float sU[DIMV*DIMV];     // 16 KB
    __shared__ float sX[8][DIMV][BB];   // 16 KB, per-warp transposed xn stage
    int bid = blockIdx.x;
    if (bid >= g_nwork) return;
    uint2 wk = g_work[bid];
    int pairStart = (int)wk.x;
    int u   = (int)(wk.y >> 16);
    int cnt = (int)(wk.y & 0xffffu);
    const float* Up = up + (size_t)u * (DIMV*DIMV);
    for (int i = threadIdx.x; i < DIMV*DIMV; i += 256) sU[i] = Up[i];
    __syncthreads();

    int w = threadIdx.x >> 5, lane = threadIdx.x & 31;
    int e2 = lane * 2;

    for (int p = w; p < cnt; p += 8) {
        unsigned pk = g_pairs[pairStart + p];
        int n = (int)(pk >> 16), m = (int)(pk & 0xffffu);
        // stage xn[:,m,:] transposed -> sX[w][d][b]
        {
            int b  = lane >> 2;
            int d0 = (lane & 3) * 16;
            const float* xr = g_xn + (b*NN + m)*DIMV + d0;
            #pragma unroll
            for (int j = 0; j < 16; j += 4) {
                float4 v = *(const float4*)(xr + j);
                sX[w][d0+j  ][b] = v.x;
                sX[w][d0+j+1][b] = v.y;
                sX[w][d0+j+2][b] = v.z;
                sX[w][d0+j+3][b] = v.w;
            }
        }
        __syncwarp();
        ull accx[4], accy[4];
        #pragma unroll
        for (int j = 0; j < 4; j++) { accx[j] = 0ull; accy[j] = 0ull; }
        #pragma unroll 8
        for (int d = 0; d < DIMV; d++) {
            float2 uu = *(const float2*)&sU[d*DIMV + e2];
            ull ux2, uy2;
            DUP2(ux2, uu.x);
            DUP2(uy2, uu.y);
            ulonglong2 xa = *(const ulonglong2*)&sX[w][d][0];  // {b0,b1},{b2,b3}
            ulonglong2 xb = *(const ulonglong2*)&sX[w][d][4];  // {b4,b5},{b6,b7}
            FMA2(accx[0], xa.x, ux2); FMA2(accy[0], xa.x, uy2);
            FMA2(accx[1], xa.y, ux2); FMA2(accy[1], xa.y, uy2);
            FMA2(accx[2], xb.x, ux2); FMA2(accy[2], xb.x, uy2);
            FMA2(accx[3], xb.y, ux2); FMA2(accy[3], xb.y, uy2);
        }
        __syncwarp();
        int base = (n*NN + m) * (BB*DIMV) + e2;
        #pragma unroll
        for (int j = 0; j < 4; j++) {
            unsigned xl, xh, yl, yh;
            asm("mov.b64 {%0,%1}, %2;" : "=r"(xl), "=r"(xh) : "l"(accx[j]));
            asm("mov.b64 {%0,%1}, %2;" : "=r"(yl), "=r"(yh) : "l"(accy[j]));
            float2 v0, v1;
            v0.x = __uint_as_float(xl); v0.y = __uint_as_float(yl);
            v1.x = __uint_as_float(xh); v1.y = __uint_as_float(yh);
            *(float2*)&g_T[base + (2*j  )*DIMV] = v0;
            *(float2*)&g_T[base + (2*j+1)*DIMV] = v1;
        }
    }
}

// ---------------- phase 2: attn-weighted sum + output projection ---------------
__global__ void k_out(const float* __restrict__ wout, const float* __restrict__ bout,
                      float* __restrict__ out) {
    __shared__ float sA[2*200];
    __shared__ float sAcc[DIMV];
    int bid = blockIdx.x;
    int b = bid / NN, n = bid % NN;
    int e = threadIdx.x;
    for (int i = e; i < 2*NN; i += DIMV) {
        int h = i / NN, m = i % NN;
        sA[h*200 + m] = g_attn[(((size_t)b*NHEAD + h)*NN + n)*NN + m];
    }
    __syncthreads();
    int h = e >> 5;
    const float* Tb = g_T + (size_t)(n*NN) * (BB*DIMV) + b*DIMV + e;
    float acc = 0.f;
    #pragma unroll 4
    for (int m = 0; m < NN; m++) acc += sA[h*200 + m] * Tb[(size_t)m * (BB*DIMV)];
    sAcc[e] = acc;
    __syncthreads();
    float r = bout[e];
    #pragma unroll 8
    for (int k = 0; k < DIMV; k++) r += sAcc[k] * wout[k*DIMV + e];
    out[(b*NN + n)*DIMV + e] = r;
}

// ---------------- launch -------------------------------------------------------
extern "C" void kernel_launch(void* const* d_in, const int* in_sizes, int n_in,
                              void* d_out, int out_size) {
    const float* x     = (const float*)d_in[0];
    const float* gamma = (const float*)d_in[1];
    const float* beta  = (const float*)d_in[2];
    const float* wqk   = (const float*)d_in[3];
    const float* up    = (const float*)d_in[4];
    const float* wout  = (const float*)d_in[5];
    const float* bout  = (const float*)d_in[6];
    float* out = (float*)d_out;

    k_fill  <<<(NPAIR+255)/256, 256>>>();
    k_plan2 <<<1, 1024>>>();
    k_ln    <<<BB*NN, 64>>>(x, gamma, beta);
    k_qk    <<<BB*NN, 128>>>(wqk);
    k_attn  <<<BB*NHEAD*25, 256>>>();
    k_main  <<<WLMAX, 256>>>(up);
    k_out   <<<BB*NN, 64>>>(wout, bout, out);
}

// round 3
// speedup vs baseline: 1.3696x; 1.2493x over previous
#include <cuda_runtime.h>
#include <cuda_fp16.h>
#include <math.h>

#define HH    14
#define WW    14
#define NN    197
#define BB    8
#define DIMV  64
#define NHEAD 2
#define DH    32
#define NUU   1122
#define NPAIR (NN*NN)   // 38809
#define RELPAIRS 38416  // 196*196
#define RELU_ 729
#define WLMAX 4096
#define NATTNBLK 400    // BB*NHEAD*25
#define SCALE 0.17677669529663687f

typedef unsigned long long ull;

// ---------------- scratch -------------------------------------------------------
__device__ float    g_xn[BB*NN*DIMV];
__device__ float    g_qk[BB*NN*2*DIMV];
__device__ float    g_attn[BB*NHEAD*NN*NN];
__device__ __half   g_T[(size_t)NPAIR*BB*DIMV];   // 39.7 MB  T[n,m,b,e] fp16
__device__ unsigned g_pairs[NPAIR];
__device__ uint2    g_work[WLMAX];
__device__ int      g_nwork;

__device__ __forceinline__ int hfun(int a) { return 14 - abs(a - 13); }
__device__ __forceinline__ int cfun(int t) {
    return (t <= 13) ? (t*(t+1))/2 : 196 - ((27-t)*(28-t))/2;
}

// ================= setup kernel: fill | plan | LN+QK (block roles) =============
// blocks 0..151   : analytic pair placement
// block  152      : work-list plan (scan)
// blocks 153..349 : fused LayerNorm + QK projection, one block per n (8 batches)
__global__ void __launch_bounds__(256) k_setup(const float* __restrict__ x,
                                               const float* __restrict__ gamma,
                                               const float* __restrict__ beta,
                                               const float* __restrict__ wqk) {
    __shared__ union {
        struct { int sa[2048]; int sb[2048]; } plan;
        struct { float sxn[BB][DIMV]; float part[2][128][BB]; } ln;
    } sm;
    int bid = blockIdx.x, t = threadIdx.x;

    if (bid < 152) {
        // ---- fill ----
        int i = bid*256 + t;
        if (i >= NPAIR) return;
        int n = i / NN, m = i % NN;
        int pos;
        if (n == 0)      pos = RELPAIRS + m;
        else if (m == 0) pos = RELPAIRS + NN + (n - 1);
        else {
            int xx = (n-1) / WW, yy = (n-1) % WW;
            int ii = (m-1) / WW, jj = (m-1) % WW;
            int dx = xx - ii + 13, dy = yy - jj + 13;
            int off = cfun(dx)*196 + hfun(dx)*cfun(dy);
            int xmin = max(0, dx-13), ymin = max(0, dy-13);
            pos = off + (xx - xmin)*hfun(dy) + (yy - ymin);
        }
        g_pairs[pos] = ((unsigned)n << 16) | (unsigned)m;
        return;
    }
    if (bid == 152) {
        // ---- plan ----
        int *src = sm.plan.sa, *dst = sm.plan.sb;
        for (int i = t; i < 2048; i += 256) {
            int c = 0;
            if (i < RELU_)    c = hfun(i/27) * hfun(i%27);
            else if (i < NUU) c = 1;
            src[i] = (c + 15) >> 4;
        }
        __syncthreads();
        for (int off = 1; off < 2048; off <<= 1) {
            for (int i = t; i < 2048; i += 256)
                dst[i] = src[i] + (i >= off ? src[i-off] : 0);
            __syncthreads();
            int* tmp = src; src = dst; dst = tmp;
        }
        for (int u = t; u < NUU; u += 256) {
            int cnt, po;
            if (u < RELU_) {
                int dx = u/27, dy = u%27;
                cnt = hfun(dx)*hfun(dy);
                po  = cfun(dx)*196 + hfun(dx)*cfun(dy);
            } else if (u < RELU_ + NN) { cnt = 1; po = RELPAIRS + (u - RELU_); }
            else                       { cnt = 1; po = RELPAIRS + NN + (u - RELU_ - NN); }
            int eo = (u == 0) ? 0 : src[u-1];
            int j = 0;
            for (int s = 0; s < cnt; s += 16, j++) {
                int c = cnt - s; if (c > 16) c = 16;
                if (eo + j < WLMAX)
                    g_work[eo + j] = make_uint2((unsigned)(po + s),
                                                ((unsigned)u << 16) | (unsigned)c);
            }
        }
        if (t == 0) g_nwork = min(src[NUU-1], WLMAX);
        return;
    }

    // ---- LN + QK : one block per token n, all 8 batches ----
    int n = bid - 153;
    int w = t >> 5, lane = t & 31;     // warp w = batch b
    {
        const float* xr = x + ((size_t)(w*NN + n))*DIMV;
        float2 v = *(const float2*)(xr + 2*lane);
        float sum = v.x + v.y, sq = v.x*v.x + v.y*v.y;
        #pragma unroll
        for (int o = 16; o > 0; o >>= 1) {
            sum += __shfl_xor_sync(0xffffffffu, sum, o);
            sq  += __shfl_xor_sync(0xffffffffu, sq,  o);
        }
        float mu  = sum * (1.0f/DIMV);
        float var = sq  * (1.0f/DIMV) - mu*mu;
        float r   = rsqrtf(var + 1e-5f);
        float2 o2;
        o2.x = (v.x - mu) * r * gamma[2*lane]   + beta[2*lane];
        o2.y = (v.y - mu) * r * gamma[2*lane+1] + beta[2*lane+1];
        sm.ln.sxn[w][2*lane]   = o2.x;
        sm.ln.sxn[w][2*lane+1] = o2.y;
        *(float2*)(g_xn + ((size_t)(w*NN + n))*DIMV + 2*lane) = o2;
    }
    __syncthreads();
    // QK: thread = (half, col): col c of wqk for all 8 batches, split d
    int c = t & 127, half = t >> 7;
    float acc[BB];
    #pragma unroll
    for (int b = 0; b < BB; b++) acc[b] = 0.f;
    int d0 = half * 32;
    #pragma unroll 8
    for (int d = 0; d < 32; d++) {
        float wv = wqk[(d0 + d)*128 + c];
        #pragma unroll
        for (int b = 0; b < BB; b++) acc[b] += sm.ln.sxn[b][d0 + d] * wv;
    }
    #pragma unroll
    for (int b = 0; b < BB; b++) sm.ln.part[half][c][b] = acc[b];
    __syncthreads();
    if (half == 0) {
        #pragma unroll
        for (int b = 0; b < BB; b++) {
            float v = sm.ln.part[0][c][b] + sm.ln.part[1][c][b];
            g_qk[((size_t)(b*NN + n))*128 + c] = v;
        }
    }
}

// ================= main kernel: attn blocks [0,400) | pair blocks [400, ...) ===
#define FMA2(acc, a, b) asm("fma.rn.f32x2 %0, %1, %2, %0;" : "+l"(acc) : "l"(a), "l"(b))

__global__ void __launch_bounds__(256) k_mainattn(const float* __restrict__ up) {
    __shared__ union {
        struct { float sU2[DIMV*128]; float sX[8][DIMV][BB]; } mn;   // 32KB + 16KB
        struct { float ks[NN*33]; float qs[DH]; float red[8]; float bcast; } at;
    } sm;
    int bid = blockIdx.x;
    int tid = threadIdx.x, lane = tid & 31, w = tid >> 5;

    if (bid < NATTNBLK) {
        // ---------------- attention scores + softmax ----------------
        int b  = bid / (NHEAD*25);
        int r  = bid % (NHEAD*25);
        int h  = r / 25;
        int nt = r % 25;
        for (int i = tid; i < NN*DH; i += 256) {
            int m = i >> 5, d = i & 31;
            sm.at.ks[m*33 + d] = g_qk[(b*NN + m)*128 + 64 + h*DH + d];
        }
        __syncthreads();
        for (int k0 = 0; k0 < 8; k0++) {
            int n = nt*8 + k0;
            if (n >= NN) break;
            if (tid < DH) sm.at.qs[tid] = g_qk[(b*NN + n)*128 + h*DH + tid];
            __syncthreads();
            float s = -3.0e38f;
            if (tid < NN) {
                float a = 0.f;
                #pragma unroll 8
                for (int d = 0; d < DH; d++) a += sm.at.qs[d] * sm.at.ks[tid*33 + d];
                s = a * SCALE;
            }
            float loc = s;
            #pragma unroll
            for (int o = 16; o > 0; o >>= 1) loc = fmaxf(loc, __shfl_xor_sync(0xffffffffu, loc, o));
            if (lane == 0) sm.at.red[w] = loc;
            __syncthreads();
            if (tid == 0) {
                float m0 = sm.at.red[0];
                #pragma unroll
                for (int i = 1; i < 8; i++) m0 = fmaxf(m0, sm.at.red[i]);
                sm.at.bcast = m0;
            }
            __syncthreads();
            float mx = sm.at.bcast;
            float p = (tid < NN) ? __expf(s - mx) : 0.f;
            float ls = p;
            #pragma unroll
            for (int o = 16; o > 0; o >>= 1) ls += __shfl_xor_sync(0xffffffffu, ls, o);
            if (lane == 0) sm.at.red[w] = ls;
            __syncthreads();
            if (tid == 0) {
                float s0 = 0.f;
                #pragma unroll
                for (int i = 0; i < 8; i++) s0 += sm.at.red[i];
                sm.at.bcast = s0;
            }
            __syncthreads();
            float inv = 1.0f / sm.at.bcast;
            if (tid < NN) g_attn[(((size_t)b*NHEAD + h)*NN + n)*NN + tid] = p * inv;
            __syncthreads();
        }
        return;
    }

    // ---------------- pair GEMM: T[n,m,b,e] = xn[b,m] . U[u][:,e] --------------
    int wid = bid - NATTNBLK;
    if (wid >= g_nwork) return;
    uint2 wk = g_work[wid];
    int pairStart = (int)wk.x;
    int u   = (int)(wk.y >> 16);
    int cnt = (int)(wk.y & 0xffffu);
    const float* Up = up + (size_t)u * (DIMV*DIMV);
    // load U, duplicated per element: sU2[d][2e]=sU2[d][2e+1]=U[d][e]
    for (int i = tid; i < DIMV*DIMV; i += 256) {
        float v = Up[i];
        int d = i >> 6, e = i & 63;
        sm.mn.sU2[d*128 + 2*e]     = v;
        sm.mn.sU2[d*128 + 2*e + 1] = v;
    }
    __syncthreads();

    int e2 = lane * 2;
    for (int p = w; p < cnt; p += 8) {
        unsigned pk = g_pairs[pairStart + p];
        int n = (int)(pk >> 16), m = (int)(pk & 0xffffu);
        {
            int b  = lane >> 2;
            int d0 = (lane & 3) * 16;
            const float* xr = g_xn + (b*NN + m)*DIMV + d0;
            #pragma unroll
            for (int j = 0; j < 16; j += 4) {
                float4 v = *(const float4*)(xr + j);
                sm.mn.sX[w][d0+j  ][b] = v.x;
                sm.mn.sX[w][d0+j+1][b] = v.y;
                sm.mn.sX[w][d0+j+2][b] = v.z;
                sm.mn.sX[w][d0+j+3][b] = v.w;
            }
        }
        __syncwarp();
        ull accx[4], accy[4];
        #pragma unroll
        for (int j = 0; j < 4; j++) { accx[j] = 0ull; accy[j] = 0ull; }
        #pragma unroll 8
        for (int d = 0; d < DIMV; d++) {
            ulonglong2 ud = *(const ulonglong2*)&sm.mn.sU2[d*128 + 2*e2]; // {ux,ux},{uy,uy}
            ulonglong2 xa = *(const ulonglong2*)&sm.mn.sX[w][d][0];
            ulonglong2 xb = *(const ulonglong2*)&sm.mn.sX[w][d][4];
            FMA2(accx[0], xa.x, ud.x); FMA2(accy[0], xa.x, ud.y);
            FMA2(accx[1], xa.y, ud.x); FMA2(accy[1], xa.y, ud.y);
            FMA2(accx[2], xb.x, ud.x); FMA2(accy[2], xb.x, ud.y);
            FMA2(accx[3], xb.y, ud.x); FMA2(accy[3], xb.y, ud.y);
        }
        __syncwarp();
        size_t base = (size_t)(n*NN + m) * (BB*DIMV) + e2;
        #pragma unroll
        for (int j = 0; j < 4; j++) {
            unsigned xl, xh, yl, yh;
            asm("mov.b64 {%0,%1}, %2;" : "=r"(xl), "=r"(xh) : "l"(accx[j]));
            asm("mov.b64 {%0,%1}, %2;" : "=r"(yl), "=r"(yh) : "l"(accy[j]));
            __half2 h0 = __floats2half2_rn(__uint_as_float(xl), __uint_as_float(yl));
            __half2 h1 = __floats2half2_rn(__uint_as_float(xh), __uint_as_float(yh));
            *(__half2*)&g_T[base + (2*j  )*DIMV] = h0;
            *(__half2*)&g_T[base + (2*j+1)*DIMV] = h1;
        }
    }
}

// ================= phase 2: attn-weighted sum + output projection ==============
// 256 threads: (e-pair p = t&31, q = t>>5) 8-way m-split for MLP
__global__ void __launch_bounds__(256) k_out(const float* __restrict__ wout,
                                             const float* __restrict__ bout,
                                             float* __restrict__ out) {
    __shared__ float sA[2*200];
    __shared__ float2 sRed[8][32];
    __shared__ float sAcc[DIMV];
    int bid = blockIdx.x;
    int b = bid / NN, n = bid % NN;
    int t = threadIdx.x;
    int p = t & 31, q = t >> 5;
    for (int i = t; i < 2*NN; i += 256) {
        int h = i / NN, m = i % NN;
        sA[h*200 + m] = g_attn[(((size_t)b*NHEAD + h)*NN + n)*NN + m];
    }
    __syncthreads();
    int e = 2*p;
    int h = e >> 5;
    const __half2* Tb = (const __half2*)(g_T + (size_t)(n*NN)*(BB*DIMV) + b*DIMV + e);
    float2 acc; acc.x = 0.f; acc.y = 0.f;
    for (int m = q; m < NN; m += 8) {
        float a = sA[h*200 + m];
        float2 v = __half22float2(Tb[(size_t)m * (BB*DIMV/2)]);
        acc.x += a * v.x;
        acc.y += a * v.y;
    }
    sRed[q][p] = acc;
    __syncthreads();
    if (t < 32) {
        float2 s = sRed[0][t];
        #pragma unroll
        for (int j = 1; j < 8; j++) { s.x += sRed[j][t].x; s.y += sRed[j][t].y; }
        sAcc[2*t] = s.x; sAcc[2*t+1] = s.y;
    }
    __syncthreads();
    if (t < DIMV) {
        float r = bout[t];
        #pragma unroll 8
        for (int k = 0; k < DIMV; k++) r += sAcc[k] * wout[k*DIMV + t];
        out[((size_t)(b*NN + n))*DIMV + t] = r;
    }
}

// ---------------- launch -------------------------------------------------------
extern "C" void kernel_launch(void* const* d_in, const int* in_sizes, int n_in,
                              void* d_out, int out_size) {
    const float* x     = (const float*)d_in[0];
    const float* gamma = (const float*)d_in[1];
    const float* beta  = (const float*)d_in[2];
    const float* wqk   = (const float*)d_in[3];
    const float* up    = (const float*)d_in[4];
    const float* wout  = (const float*)d_in[5];
    const float* bout  = (const float*)d_in[6];
    float* out = (float*)d_out;

    k_setup   <<<153 + NN, 256>>>(x, gamma, beta, wqk);
    k_mainattn<<<NATTNBLK + WLMAX, 256>>>(up);
    k_out     <<<BB*NN, 256>>>(wout, bout, out);
}